// round 6
// baseline (speedup 1.0000x reference)
#include <cuda_runtime.h>
#include <stdint.h>

#define N_PTS 16384
#define TPB 256
#define QPT 8                              // query points per thread
#define J_TILE 256                         // db points per block tile
#define J_SPLITS (N_PTS / J_TILE)          // 64
#define I_BLOCKS (N_PTS / (TPB * QPT))     // 8
#define R1_BLOCKS 128

// Partial results: max_j (a.b_j - 0.5|b_j|^2) per (direction, j-split, point).
// Every slot written exactly once by its block -> no init, no atomics.
__device__ float g_part[2][J_SPLITS][N_PTS];   // 8 MB (L2-resident)
__device__ float g_bsum[R1_BLOCKS];

__device__ __forceinline__ unsigned long long pack2(float lo, float hi) {
    unsigned long long r;
    asm("mov.b64 %0, {%1, %2};" : "=l"(r) : "f"(lo), "f"(hi));
    return r;
}
__device__ __forceinline__ unsigned long long fma2(
    unsigned long long a, unsigned long long b, unsigned long long c) {
    unsigned long long d;
    asm("fma.rn.f32x2 %0, %1, %2, %3;" : "=l"(d) : "l"(a), "l"(b), "l"(c));
    return d;
}
__device__ __forceinline__ void unpack2(unsigned long long v, float& lo, float& hi) {
    asm("mov.b64 {%0, %1}, %2;" : "=f"(lo), "=f"(hi) : "l"(v));
}

__global__ void __launch_bounds__(TPB) cd_pass_kernel(
    const float* __restrict__ pred, const float* __restrict__ gt)
{
    // z=0: query=pred, db=gt; z=1: query=gt, db=pred
    const float* __restrict__ A = (blockIdx.z == 0) ? pred : gt;
    const float* __restrict__ B = (blockIdx.z == 0) ? gt : pred;

    // db tile, 2 points packed per entry: (x0,x1),(y0,y1) and (z0,z1),(c0,c1)
    // with c = -0.5*|b|^2 (negated so it drops straight into the first fma).
    __shared__ ulonglong2 tile_xy[J_TILE / 2];
    __shared__ ulonglong2 tile_zc[J_TILE / 2];

    const int t = threadIdx.x;
    const int jbase = blockIdx.y * J_TILE;
    if (t < J_TILE / 2) {
        const float* bp = B + 3 * (jbase + 2 * t);
        float x0 = bp[0], y0 = bp[1], z0 = bp[2];
        float x1 = bp[3], y1 = bp[4], z1 = bp[5];
        float c0 = -0.5f * fmaf(x0, x0, fmaf(y0, y0, z0 * z0));
        float c1 = -0.5f * fmaf(x1, x1, fmaf(y1, y1, z1 * z1));
        tile_xy[t] = make_ulonglong2(pack2(x0, x1), pack2(y0, y1));
        tile_zc[t] = make_ulonglong2(pack2(z0, z1), pack2(c0, c1));
    }

    // 8 query points per thread, broadcast-packed (a,a) once: 24 floats = 6 float4.
    const int i0 = (blockIdx.x * TPB + t) * QPT;
    float q[3 * QPT];
#pragma unroll
    for (int v = 0; v < 6; ++v)
        *(float4*)&q[4 * v] = *(const float4*)(A + 3 * i0 + 4 * v);

    unsigned long long qx[QPT], qy[QPT], qz[QPT];
#pragma unroll
    for (int k = 0; k < QPT; ++k) {
        qx[k] = pack2(q[3 * k + 0], q[3 * k + 0]);
        qy[k] = pack2(q[3 * k + 1], q[3 * k + 1]);
        qz[k] = pack2(q[3 * k + 2], q[3 * k + 2]);
    }

    float best0[QPT], best1[QPT];
#pragma unroll
    for (int k = 0; k < QPT; ++k) { best0[k] = -3.402823466e+38f; best1[k] = -3.402823466e+38f; }

    __syncthreads();

    // min_j ||a-b_j||^2 = |a|^2 - 2 * max_j (a.b_j - 0.5|b_j|^2)
#pragma unroll 4
    for (int p = 0; p < J_TILE / 2; ++p) {
        const ulonglong2 xy = tile_xy[p];   // LDS.128 broadcast
        const ulonglong2 zc = tile_zc[p];   // LDS.128 broadcast
#pragma unroll
        for (int k = 0; k < QPT; ++k) {
            unsigned long long tt = fma2(qx[k], xy.x, zc.y);
            tt = fma2(qy[k], xy.y, tt);
            tt = fma2(qz[k], zc.x, tt);
            float t0, t1;
            unpack2(tt, t0, t1);            // reg-pair aliasing, free in SASS
            best0[k] = fmaxf(best0[k], t0);
            best1[k] = fmaxf(best1[k], t1);
        }
    }

    float outv[QPT];
#pragma unroll
    for (int k = 0; k < QPT; ++k) outv[k] = fmaxf(best0[k], best1[k]);
    float* dst = &g_part[blockIdx.z][blockIdx.y][i0];
    *(float4*)(dst)     = *(float4*)&outv[0];
    *(float4*)(dst + 4) = *(float4*)&outv[4];
}

__global__ void __launch_bounds__(TPB) cd_reduce1_kernel(
    const float* __restrict__ pred, const float* __restrict__ gt)
{
    const int gidx = blockIdx.x * TPB + threadIdx.x;   // 0 .. 32767
    const int z = gidx >> 14;
    const int i = gidx & (N_PTS - 1);

    float m = -3.402823466e+38f;
#pragma unroll 16
    for (int j = 0; j < J_SPLITS; ++j) m = fmaxf(m, g_part[z][j][i]);

    const float* __restrict__ A = (z == 0) ? pred : gt;
    const float ax = A[3 * i], ay = A[3 * i + 1], az = A[3 * i + 2];
    const float a2 = fmaf(ax, ax, fmaf(ay, ay, az * az));
    float s = sqrtf(fmaxf(fmaf(-2.0f, m, a2), 0.0f));

    // block sum
    __shared__ float ssum[TPB / 32];
    for (int o = 16; o > 0; o >>= 1) s += __shfl_xor_sync(0xFFFFFFFFu, s, o);
    if ((threadIdx.x & 31) == 0) ssum[threadIdx.x >> 5] = s;
    __syncthreads();
    if (threadIdx.x == 0) {
        float tot = 0.0f;
        for (int w = 0; w < TPB / 32; ++w) tot += ssum[w];
        g_bsum[blockIdx.x] = tot;
    }
}

__global__ void cd_reduce2_kernel(float* __restrict__ out) {
    float s = g_bsum[threadIdx.x];   // 128 threads, 128 partials
    for (int o = 16; o > 0; o >>= 1) s += __shfl_xor_sync(0xFFFFFFFFu, s, o);
    __shared__ float ssum[4];
    if ((threadIdx.x & 31) == 0) ssum[threadIdx.x >> 5] = s;
    __syncthreads();
    if (threadIdx.x == 0) {
        float tot = ssum[0] + ssum[1] + ssum[2] + ssum[3];
        out[0] = tot / (float)N_PTS;   // (sum1 + sum2)/N = mean1 + mean2
    }
}

extern "C" void kernel_launch(void* const* d_in, const int* in_sizes, int n_in,
                              void* d_out, int out_size) {
    const float* pred = (const float*)d_in[0];
    const float* gt   = (const float*)d_in[1];
    float* out = (float*)d_out;

    dim3 grid(I_BLOCKS, J_SPLITS, 2);          // (8, 64, 2) = 1024 blocks
    cd_pass_kernel<<<grid, TPB>>>(pred, gt);
    cd_reduce1_kernel<<<R1_BLOCKS, TPB>>>(pred, gt);
    cd_reduce2_kernel<<<1, 128>>>(out);
}